// round 1
// baseline (speedup 1.0000x reference)
#include <cuda_runtime.h>
#include <cuda_bf16.h>
#include <math.h>

// ---------------- problem constants ----------------
#define LAYERS 4
#define D 768
#define H 12
#define HD 64
#define V 50257
#define B 2
#define T 1024
#define M (B*T)          // 2048 rows
#define D3 (3*D)         // 2304
#define D4 (4*D)         // 3072
#define EPS 1e-5f

// ---------------- scratch (device globals; no allocation) ----------------
__device__ float g_x   [(size_t)M * D];    // residual stream
__device__ float g_ln  [(size_t)M * D];    // layernorm output
__device__ float g_qkv [(size_t)M * D3];   // qkv projection
__device__ float g_attn[(size_t)M * D];    // attention output
__device__ float g_big [(size_t)M * D4];   // mlp hidden (gelu'd)

// ---------------- embedding: x = wte[ids] + wpe[t] ----------------
__global__ void embed_kernel(const int* __restrict__ ids,
                             const float* __restrict__ wte,
                             const float* __restrict__ wpe)
{
    int row = blockIdx.x;            // 0..M-1
    int t   = row % T;
    int id  = ids[row];
    const float* we = wte + (size_t)id * D;
    const float* pe = wpe + (size_t)t  * D;
    float* out = g_x + (size_t)row * D;
    for (int i = threadIdx.x; i < D; i += blockDim.x)
        out[i] = we[i] + pe[i];
}

// ---------------- layernorm: one block per row ----------------
__global__ void layernorm_kernel(const float* __restrict__ x,
                                 const float* __restrict__ g,
                                 const float* __restrict__ b,
                                 float* __restrict__ out)
{
    int row = blockIdx.x;
    int tid = threadIdx.x;           // 256 threads
    const float* xr = x + (size_t)row * D;
    __shared__ float red[256];

    float s = 0.f;
    for (int i = tid; i < D; i += 256) s += xr[i];
    red[tid] = s; __syncthreads();
    for (int st = 128; st > 0; st >>= 1) {
        if (tid < st) red[tid] += red[tid + st];
        __syncthreads();
    }
    float mu = red[0] / (float)D;
    __syncthreads();

    float v = 0.f;
    for (int i = tid; i < D; i += 256) { float d = xr[i] - mu; v += d * d; }
    red[tid] = v; __syncthreads();
    for (int st = 128; st > 0; st >>= 1) {
        if (tid < st) red[tid] += red[tid + st];
        __syncthreads();
    }
    float rstd = rsqrtf(red[0] / (float)D + EPS);

    float* o = out + (size_t)row * D;
    for (int i = tid; i < D; i += 256)
        o[i] = g[i] * (xr[i] - mu) * rstd + b[i];
}

// ---------------- tiled SGEMM ----------------
// C[M,N] = A[M,K] @ W + bias (+ GELU) (+ residual accumulate into C)
// WT=false: W is [K,N] row-major.  WT=true: W is [N,K] row-major (B^T GEMM, used for lm_head).
// flags: bit0 = exact GELU epilogue, bit1 = C += result (residual add; C pre-holds residual)
#define BM 128
#define BN 128
#define BKT 16
#define FLAG_GELU  1
#define FLAG_ACCUM 2

template<bool WT>
__global__ __launch_bounds__(256)
void gemm_kernel(const float* __restrict__ A, const float* __restrict__ W,
                 const float* __restrict__ bias, float* __restrict__ C,
                 int Mm, int N, int K, int flags)
{
    __shared__ float As[BKT][BM + 4];
    __shared__ float Ws[BKT][BN + 4];

    int tid = threadIdx.x;
    int m0 = blockIdx.y * BM;
    int n0 = blockIdx.x * BN;
    int tx = tid & 15;     // 0..15 -> n
    int ty = tid >> 4;     // 0..15 -> m

    float acc[8][8];
    #pragma unroll
    for (int i = 0; i < 8; i++)
        #pragma unroll
        for (int j = 0; j < 8; j++) acc[i][j] = 0.f;

    for (int k0 = 0; k0 < K; k0 += BKT) {
        // ---- load A tile (BM x BKT), float4 along K ----
        {
            int r  = tid >> 2;          // 0..63
            int c4 = (tid & 3) * 4;     // 0,4,8,12
            #pragma unroll
            for (int rr = 0; rr < 2; rr++) {
                int row = r + rr * 64;
                float4 v = *(const float4*)(A + (size_t)(m0 + row) * K + k0 + c4);
                As[c4 + 0][row] = v.x; As[c4 + 1][row] = v.y;
                As[c4 + 2][row] = v.z; As[c4 + 3][row] = v.w;
            }
        }
        if (!WT) {
            // ---- W[K,N] tile (BKT x BN), float4 along N; N % 128 == 0 here ----
            int kk = tid >> 5;          // 0..7
            int n4 = (tid & 31) * 4;
            #pragma unroll
            for (int rr = 0; rr < 2; rr++) {
                int k = kk + rr * 8;
                float4 v = *(const float4*)(W + (size_t)(k0 + k) * N + n0 + n4);
                Ws[k][n4 + 0] = v.x; Ws[k][n4 + 1] = v.y;
                Ws[k][n4 + 2] = v.z; Ws[k][n4 + 3] = v.w;
            }
        } else {
            // ---- W[N,K] tile (BN x BKT), float4 along K; guard n (V=50257) ----
            int r  = tid >> 2;
            int c4 = (tid & 3) * 4;
            #pragma unroll
            for (int rr = 0; rr < 2; rr++) {
                int n = r + rr * 64;
                float4 v;
                if (n0 + n < N) v = *(const float4*)(W + (size_t)(n0 + n) * K + k0 + c4);
                else            v = make_float4(0.f, 0.f, 0.f, 0.f);
                Ws[c4 + 0][n] = v.x; Ws[c4 + 1][n] = v.y;
                Ws[c4 + 2][n] = v.z; Ws[c4 + 3][n] = v.w;
            }
        }
        __syncthreads();

        #pragma unroll
        for (int k = 0; k < BKT; k++) {
            float ra[8], rb[8];
            #pragma unroll
            for (int i = 0; i < 8; i++) ra[i] = As[k][ty * 8 + i];
            #pragma unroll
            for (int j = 0; j < 8; j++) rb[j] = Ws[k][tx * 8 + j];
            #pragma unroll
            for (int i = 0; i < 8; i++)
                #pragma unroll
                for (int j = 0; j < 8; j++)
                    acc[i][j] = fmaf(ra[i], rb[j], acc[i][j]);
        }
        __syncthreads();
    }

    // ---- epilogue ----
    #pragma unroll
    for (int i = 0; i < 8; i++) {
        int m = m0 + ty * 8 + i;
        #pragma unroll
        for (int j = 0; j < 8; j++) {
            int n = n0 + tx * 8 + j;
            if (WT && n >= N) continue;
            float v = acc[i][j];
            if (bias) v += bias[n];
            if (flags & FLAG_GELU)
                v = 0.5f * v * (1.f + erff(v * 0.70710678118654752f));
            size_t idx = (size_t)m * N + n;
            if (flags & FLAG_ACCUM) v += C[idx];
            C[idx] = v;
        }
    }
}

// ---------------- fused causal attention: one block per (b,h,q) ----------------
__global__ __launch_bounds__(128)
void attention_kernel(const float* __restrict__ qkv, float* __restrict__ out)
{
    int q  = blockIdx.x;            // 0..T-1
    int bh = blockIdx.y;            // 0..B*H-1
    int b  = bh / H, h = bh % H;
    int tid = threadIdx.x;          // 128

    __shared__ float qs[HD];
    __shared__ float sc[T];
    __shared__ float red[128];

    const float* base = qkv + (size_t)b * T * D3;
    if (tid < HD) qs[tid] = base[(size_t)q * D3 + h * HD + tid];
    __syncthreads();

    int nk = q + 1;
    const float scale = 0.125f;      // 1/sqrt(64)

    // scores
    for (int k = tid; k < nk; k += 128) {
        const float* kr = base + (size_t)k * D3 + D + h * HD;
        float s = 0.f;
        #pragma unroll
        for (int d = 0; d < HD; d++) s = fmaf(qs[d], kr[d], s);
        sc[k] = s * scale;
    }
    __syncthreads();

    // max
    float mx = -1e30f;
    for (int k = tid; k < nk; k += 128) mx = fmaxf(mx, sc[k]);
    red[tid] = mx; __syncthreads();
    for (int s = 64; s > 0; s >>= 1) {
        if (tid < s) red[tid] = fmaxf(red[tid], red[tid + s]);
        __syncthreads();
    }
    mx = red[0];
    __syncthreads();

    // exp + sum
    float sum = 0.f;
    for (int k = tid; k < nk; k += 128) {
        float e = __expf(sc[k] - mx);
        sc[k] = e;
        sum += e;
    }
    red[tid] = sum; __syncthreads();
    for (int s = 64; s > 0; s >>= 1) {
        if (tid < s) red[tid] += red[tid + s];
        __syncthreads();
    }
    float inv = 1.f / red[0];
    __syncthreads();

    // AV: 2 key-strided partials per head-dim
    int d = tid & 63, half = tid >> 6;
    float acc = 0.f;
    const float* vbase = base + D + D + (size_t)h * HD + d;   // v offset 2*D within qkv row
    for (int k = half; k < nk; k += 2)
        acc = fmaf(sc[k], vbase[(size_t)k * D3], acc);
    red[tid] = acc;
    __syncthreads();
    if (tid < 64)
        out[(size_t)(b * T + q) * D + h * HD + d] = (red[d] + red[d + 64]) * inv;
}

// ---------------- host side ----------------
static inline void launch_gemm_nt(const float* A, const float* W, const float* bias,
                                  float* C, int Mm, int N, int K, int flags)
{
    dim3 grid(N / BN, Mm / BM);
    gemm_kernel<false><<<grid, 256>>>(A, W, bias, C, Mm, N, K, flags);
}
static inline void launch_gemm_tt(const float* A, const float* W, const float* bias,
                                  float* C, int Mm, int N, int K, int flags)
{
    dim3 grid((N + BN - 1) / BN, Mm / BM);
    gemm_kernel<true><<<grid, 256>>>(A, W, bias, C, Mm, N, K, flags);
}

extern "C" void kernel_launch(void* const* d_in, const int* in_sizes, int n_in,
                              void* d_out, int out_size)
{
    const int*   ids    = (const int*)  d_in[0];
    const float* wte    = (const float*)d_in[1];
    const float* wpe    = (const float*)d_in[2];
    const float* ln1_g  = (const float*)d_in[3];
    const float* ln1_b  = (const float*)d_in[4];
    const float* attn_w = (const float*)d_in[5];
    const float* attn_b = (const float*)d_in[6];
    const float* proj_w = (const float*)d_in[7];
    const float* proj_b = (const float*)d_in[8];
    const float* ln2_g  = (const float*)d_in[9];
    const float* ln2_b  = (const float*)d_in[10];
    const float* fc_w   = (const float*)d_in[11];
    const float* fc_b   = (const float*)d_in[12];
    const float* out_w  = (const float*)d_in[13];
    const float* out_b  = (const float*)d_in[14];
    const float* lnf_g  = (const float*)d_in[15];
    const float* lnf_b  = (const float*)d_in[16];
    float* logits = (float*)d_out;

    float *x, *ln, *qkv, *attn, *big;
    cudaGetSymbolAddress((void**)&x,    g_x);
    cudaGetSymbolAddress((void**)&ln,   g_ln);
    cudaGetSymbolAddress((void**)&qkv,  g_qkv);
    cudaGetSymbolAddress((void**)&attn, g_attn);
    cudaGetSymbolAddress((void**)&big,  g_big);

    // embedding
    embed_kernel<<<M, 256>>>(ids, wte, wpe);

    for (int l = 0; l < LAYERS; l++) {
        const float* aw = attn_w + (size_t)l * D * D3;
        const float* ab = attn_b + (size_t)l * D3;
        const float* pw = proj_w + (size_t)l * D * D;
        const float* pb = proj_b + (size_t)l * D;
        const float* fw = fc_w   + (size_t)l * D * D4;
        const float* fb = fc_b   + (size_t)l * D4;
        const float* ow = out_w  + (size_t)l * D4 * D;
        const float* ob = out_b  + (size_t)l * D;

        // attention block
        layernorm_kernel<<<M, 256>>>(x, ln1_g + (size_t)l * D, ln1_b + (size_t)l * D, ln);
        launch_gemm_nt(ln, aw, ab, qkv, M, D3, D, 0);
        {
            dim3 grid(T, B * H);
            attention_kernel<<<grid, 128>>>(qkv, attn);
        }
        launch_gemm_nt(attn, pw, pb, x, M, D, D, FLAG_ACCUM);

        // mlp block
        layernorm_kernel<<<M, 256>>>(x, ln2_g + (size_t)l * D, ln2_b + (size_t)l * D, ln);
        launch_gemm_nt(ln, fw, fb, big, M, D4, D, FLAG_GELU);
        launch_gemm_nt(big, ow, ob, x, M, D, D4, FLAG_ACCUM);
    }

    // final ln + tied lm_head (x @ wte^T)
    layernorm_kernel<<<M, 256>>>(x, lnf_g, lnf_b, ln);
    launch_gemm_tt(ln, wte, nullptr, logits, M, V, D, 0);
}

// round 4
// speedup vs baseline: 2.6080x; 2.6080x over previous
#include <cuda_runtime.h>
#include <cuda_bf16.h>
#include <math.h>
#include <stdint.h>

// ---------------- problem constants ----------------
#define LAYERS 4
#define D 768
#define H 12
#define HD 64
#define V 50257
#define B 2
#define T 1024
#define M (B*T)          // 2048 rows
#define D3 (3*D)         // 2304
#define D4 (4*D)         // 3072
#define EPS 1e-5f

#define FLAG_GELU  1
#define FLAG_ACCUM 2

// ---------------- scratch (device globals; no allocation) ----------------
__device__ float g_x   [(size_t)M * D];
__device__ float g_ln  [(size_t)M * D];
__device__ float g_attn[(size_t)M * D];
__device__ float g_qkv [(size_t)M * D3];
__device__ float g_big [(size_t)M * D4];
__device__ __nv_bfloat16 g_ahi[(size_t)M * D4];
__device__ __nv_bfloat16 g_alo[(size_t)M * D4];
__device__ __nv_bfloat16 g_whi[(size_t)V * D];   // per-layer W^T splits, then wte split
__device__ __nv_bfloat16 g_wlo[(size_t)V * D];

__device__ __forceinline__ uint32_t smem_u32(const void* p) {
    uint32_t a;
    asm("{ .reg .u64 t; cvta.to.shared.u64 t, %1; cvt.u32.u64 %0, t; }" : "=r"(a) : "l"(p));
    return a;
}

// ---------------- embedding ----------------
__global__ void embed_kernel(const int* __restrict__ ids,
                             const float* __restrict__ wte,
                             const float* __restrict__ wpe)
{
    int row = blockIdx.x;
    int t   = row % T;
    int id  = ids[row];
    const float* we = wte + (size_t)id * D;
    const float* pe = wpe + (size_t)t  * D;
    float* out = g_x + (size_t)row * D;
    for (int i = threadIdx.x; i < D; i += blockDim.x)
        out[i] = we[i] + pe[i];
}

// ---------------- layernorm ----------------
__global__ void layernorm_kernel(const float* __restrict__ x,
                                 const float* __restrict__ g,
                                 const float* __restrict__ b,
                                 float* __restrict__ out)
{
    int row = blockIdx.x;
    int tid = threadIdx.x;
    const float* xr = x + (size_t)row * D;
    __shared__ float red[256];

    float s = 0.f;
    for (int i = tid; i < D; i += 256) s += xr[i];
    red[tid] = s; __syncthreads();
    for (int st = 128; st > 0; st >>= 1) { if (tid < st) red[tid] += red[tid + st]; __syncthreads(); }
    float mu = red[0] / (float)D;
    __syncthreads();

    float v = 0.f;
    for (int i = tid; i < D; i += 256) { float d = xr[i] - mu; v += d * d; }
    red[tid] = v; __syncthreads();
    for (int st = 128; st > 0; st >>= 1) { if (tid < st) red[tid] += red[tid + st]; __syncthreads(); }
    float rstd = rsqrtf(red[0] / (float)D + EPS);

    float* o = out + (size_t)row * D;
    for (int i = tid; i < D; i += 256)
        o[i] = g[i] * (xr[i] - mu) * rstd + b[i];
}

// ---------------- fp32 -> bf16 hi/lo split ----------------
__global__ void split_kernel(const float* __restrict__ X,
                             __nv_bfloat16* __restrict__ hi,
                             __nv_bfloat16* __restrict__ lo, int n4)
{
    int i = blockIdx.x * blockDim.x + threadIdx.x;
    if (i >= n4) return;
    float4 v = ((const float4*)X)[i];
    float f[4] = {v.x, v.y, v.z, v.w};
    __nv_bfloat16 h[4], l[4];
    #pragma unroll
    for (int j = 0; j < 4; j++) {
        h[j] = __float2bfloat16(f[j]);
        l[j] = __float2bfloat16(f[j] - __bfloat162float(h[j]));
    }
    *(uint2*)(hi + 4 * (size_t)i) = *(uint2*)h;
    *(uint2*)(lo + 4 * (size_t)i) = *(uint2*)l;
}

// ---------------- W[K,N] -> hi/lo[N,K] transpose + split ----------------
__global__ void wsplit_t_kernel(const float* __restrict__ W,
                                __nv_bfloat16* __restrict__ hi,
                                __nv_bfloat16* __restrict__ lo, int K, int N)
{
    __shared__ float tb[32][33];
    int n0 = blockIdx.x * 32, k0 = blockIdx.y * 32;
    int tx = threadIdx.x, ty = threadIdx.y;    // (32, 8)
    #pragma unroll
    for (int i = 0; i < 4; i++)
        tb[ty + i * 8][tx] = W[(size_t)(k0 + ty + i * 8) * N + n0 + tx];
    __syncthreads();
    #pragma unroll
    for (int i = 0; i < 4; i++) {
        int n = n0 + ty + i * 8, k = k0 + tx;
        float v = tb[tx][ty + i * 8];
        __nv_bfloat16 h = __float2bfloat16(v);
        hi[(size_t)n * K + k] = h;
        lo[(size_t)n * K + k] = __float2bfloat16(v - __bfloat162float(h));
    }
}

// ---------------- mma.sync GEMM: C[M,N] = (Ahi+Alo)[M,K] @ (Bhi+Blo)[N,K]^T ----------------
// 3 K-passes (hi*hi, hi*lo, lo*hi) accumulated in registers.
#define BM 128
#define BN 128
#define BK 32
#define STAGES 3
#define ROWB 80                    // (32+8 pad) bf16 = 80 bytes per row, 16B-aligned
#define TILEB (BM*ROWB)            // 10240 B per tile-stage
#define SMEM_TOTAL (2*STAGES*TILEB)  // 61440 B

__global__ void __launch_bounds__(256)
gemm_mma(const __nv_bfloat16* __restrict__ Ahi, const __nv_bfloat16* __restrict__ Alo,
         const __nv_bfloat16* __restrict__ Bhi, const __nv_bfloat16* __restrict__ Blo,
         const float* __restrict__ bias, float* __restrict__ C,
         int N, int K, int flags)
{
    extern __shared__ char smem[];
    const uint32_t sbase = smem_u32(smem);
    const int tid = threadIdx.x, lane = tid & 31, wid = tid >> 5;
    const int wm = wid & 3, wn = wid >> 2;        // 4x2 warp grid: 32-row x 64-col warp tiles
    const int m0 = blockIdx.y * BM, n0 = blockIdx.x * BN;
    const int KT = K / BK, nt = 3 * KT;

    float acc[2][8][4];
    #pragma unroll
    for (int i = 0; i < 2; i++)
        #pragma unroll
        for (int j = 0; j < 8; j++)
            #pragma unroll
            for (int c = 0; c < 4; c++) acc[i][j][c] = 0.f;

    // per-thread load coords (2 x 16B chunks per thread per tile)
    auto issue = [&](int t, int s) {
        int p = t / KT, kt = t - p * KT, kb = kt * BK;
        const __nv_bfloat16* Ap = (p == 2) ? Alo : Ahi;
        const __nv_bfloat16* Bp = (p == 1) ? Blo : Bhi;
        uint32_t sa = sbase + s * TILEB;
        uint32_t sbm = sbase + STAGES * TILEB + s * TILEB;
        #pragma unroll
        for (int j = 0; j < 2; j++) {
            int id = tid + 256 * j;
            int row = id >> 2, c = id & 3;
            uint32_t da = sa + row * ROWB + c * 16;
            const void* ga = Ap + (size_t)(m0 + row) * K + kb + c * 8;
            asm volatile("cp.async.cg.shared.global [%0], [%1], 16;" :: "r"(da), "l"(ga));
            int bn = n0 + row;
            uint32_t db = sbm + row * ROWB + c * 16;
            const void* gb = Bp + (size_t)(bn < N ? bn : 0) * K + kb + c * 8;
            int sz = (bn < N) ? 16 : 0;
            asm volatile("cp.async.cg.shared.global [%0], [%1], 16, %2;" :: "r"(db), "l"(gb), "r"(sz));
        }
    };

    const int lrow = lane & 15, lhalf = lane >> 4;

    issue(0, 0);
    asm volatile("cp.async.commit_group;" ::: "memory");
    issue(1, 1);
    asm volatile("cp.async.commit_group;" ::: "memory");

    for (int t = 0; t < nt; t++) {
        asm volatile("cp.async.wait_group 1;" ::: "memory");
        __syncthreads();

        int tn = t + STAGES - 1;
        if (tn < nt) issue(tn, tn % STAGES);
        asm volatile("cp.async.commit_group;" ::: "memory");

        // ---- compute stage s = t % STAGES ----
        {
            int s = t % STAGES;
            uint32_t sa = sbase + s * TILEB + (wm * 32 + lrow) * ROWB + lhalf * 16;
            uint32_t sbm = sbase + STAGES * TILEB + s * TILEB + (wn * 64 + lrow) * ROWB + lhalf * 16;
            #pragma unroll
            for (int kk = 0; kk < 2; kk++) {
                uint32_t a[2][4], b[4][4];
                int koff = kk * 32;
                #pragma unroll
                for (int mi = 0; mi < 2; mi++) {
                    uint32_t ad = sa + mi * 16 * ROWB + koff;
                    asm volatile("ldmatrix.sync.aligned.m8n8.x4.shared.b16 {%0,%1,%2,%3}, [%4];"
                        : "=r"(a[mi][0]), "=r"(a[mi][1]), "=r"(a[mi][2]), "=r"(a[mi][3]) : "r"(ad));
                }
                #pragma unroll
                for (int nt4 = 0; nt4 < 4; nt4++) {
                    uint32_t bd = sbm + nt4 * 16 * ROWB + koff;
                    asm volatile("ldmatrix.sync.aligned.m8n8.x4.shared.b16 {%0,%1,%2,%3}, [%4];"
                        : "=r"(b[nt4][0]), "=r"(b[nt4][1]), "=r"(b[nt4][2]), "=r"(b[nt4][3]) : "r"(bd));
                }
                #pragma unroll
                for (int mi = 0; mi < 2; mi++) {
                    #pragma unroll
                    for (int nj = 0; nj < 8; nj++) {
                        int n4 = nj >> 1, odd = nj & 1;
                        uint32_t b0 = odd ? b[n4][1] : b[n4][0];
                        uint32_t b1 = odd ? b[n4][3] : b[n4][2];
                        asm volatile(
                            "mma.sync.aligned.m16n8k16.row.col.f32.bf16.bf16.f32 "
                            "{%0,%1,%2,%3}, {%4,%5,%6,%7}, {%8,%9}, {%0,%1,%2,%3};"
                            : "+f"(acc[mi][nj][0]), "+f"(acc[mi][nj][1]),
                              "+f"(acc[mi][nj][2]), "+f"(acc[mi][nj][3])
                            : "r"(a[mi][0]), "r"(a[mi][1]), "r"(a[mi][2]), "r"(a[mi][3]),
                              "r"(b0), "r"(b1));
                    }
                }
            }
        }
        __syncthreads();
    }

    // ---- epilogue ----
    int mrow = m0 + wm * 32 + (lane >> 2);
    int ncol = n0 + wn * 64 + (lane & 3) * 2;
    #pragma unroll
    for (int mi = 0; mi < 2; mi++) {
        int r0 = mrow + mi * 16;
        #pragma unroll
        for (int nj = 0; nj < 8; nj++) {
            int cb = ncol + nj * 8;
            #pragma unroll
            for (int half = 0; half < 2; half++) {
                int r = r0 + half * 8;
                float* Crow = C + (size_t)r * N;
                #pragma unroll
                for (int e = 0; e < 2; e++) {
                    int n = cb + e;
                    if (n < N) {
                        float v = acc[mi][nj][half * 2 + e];
                        if (bias) v += bias[n];
                        if (flags & FLAG_GELU)
                            v = 0.5f * v * (1.f + erff(v * 0.70710678118654752f));
                        if (flags & FLAG_ACCUM) v += Crow[n];
                        Crow[n] = v;
                    }
                }
            }
        }
    }
}

// ---------------- fused causal attention ----------------
__global__ __launch_bounds__(128)
void attention_kernel(const float* __restrict__ qkv, float* __restrict__ out)
{
    int q  = blockIdx.x;
    int bh = blockIdx.y;
    int b  = bh / H, h = bh % H;
    int tid = threadIdx.x;

    __shared__ float4 qs4[16];
    __shared__ float sc[T];
    __shared__ float red[128];

    const float* base = qkv + (size_t)b * T * D3;
    if (tid < 16) qs4[tid] = ((const float4*)(base + (size_t)q * D3 + h * HD))[tid];
    __syncthreads();

    int nk = q + 1;
    const float scale = 0.125f;

    for (int k = tid; k < nk; k += 128) {
        const float4* kr = (const float4*)(base + (size_t)k * D3 + D + h * HD);
        float s = 0.f;
        #pragma unroll
        for (int d = 0; d < 16; d++) {
            float4 kv = kr[d], qv = qs4[d];
            s += qv.x * kv.x + qv.y * kv.y + qv.z * kv.z + qv.w * kv.w;
        }
        sc[k] = s * scale;
    }
    __syncthreads();

    float mx = -1e30f;
    for (int k = tid; k < nk; k += 128) mx = fmaxf(mx, sc[k]);
    red[tid] = mx; __syncthreads();
    for (int s = 64; s > 0; s >>= 1) { if (tid < s) red[tid] = fmaxf(red[tid], red[tid + s]); __syncthreads(); }
    mx = red[0];
    __syncthreads();

    float sum = 0.f;
    for (int k = tid; k < nk; k += 128) {
        float e = __expf(sc[k] - mx);
        sc[k] = e;
        sum += e;
    }
    red[tid] = sum; __syncthreads();
    for (int s = 64; s > 0; s >>= 1) { if (tid < s) red[tid] += red[tid + s]; __syncthreads(); }
    float inv = 1.f / red[0];
    __syncthreads();

    int d = tid & 63, half = tid >> 6;
    float acc = 0.f;
    const float* vbase = base + D + D + (size_t)h * HD + d;
    for (int k = half; k < nk; k += 2)
        acc = fmaf(sc[k], vbase[(size_t)k * D3], acc);
    red[tid] = acc;
    __syncthreads();
    if (tid < 64)
        out[(size_t)(b * T + q) * D + h * HD + d] = (red[d] + red[d + 64]) * inv;
}

// ---------------- host side ----------------
static inline void run_gemm(const __nv_bfloat16* Ahi, const __nv_bfloat16* Alo,
                            const __nv_bfloat16* Bhi, const __nv_bfloat16* Blo,
                            const float* bias, float* C, int N, int K, int flags)
{
    dim3 grid((N + BN - 1) / BN, M / BM);
    gemm_mma<<<grid, 256, SMEM_TOTAL>>>(Ahi, Alo, Bhi, Blo, bias, C, N, K, flags);
}
static inline void run_split(const float* X, __nv_bfloat16* hi, __nv_bfloat16* lo, size_t n)
{
    int n4 = (int)(n / 4);
    split_kernel<<<(n4 + 255) / 256, 256>>>(X, hi, lo, n4);
}
static inline void run_wsplit(const float* W, __nv_bfloat16* hi, __nv_bfloat16* lo, int K, int N)
{
    dim3 grid(N / 32, K / 32);
    wsplit_t_kernel<<<grid, dim3(32, 8)>>>(W, hi, lo, K, N);
}

extern "C" void kernel_launch(void* const* d_in, const int* in_sizes, int n_in,
                              void* d_out, int out_size)
{
    const int*   ids    = (const int*)  d_in[0];
    const float* wte    = (const float*)d_in[1];
    const float* wpe    = (const float*)d_in[2];
    const float* ln1_g  = (const float*)d_in[3];
    const float* ln1_b  = (const float*)d_in[4];
    const float* attn_w = (const float*)d_in[5];
    const float* attn_b = (const float*)d_in[6];
    const float* proj_w = (const float*)d_in[7];
    const float* proj_b = (const float*)d_in[8];
    const float* ln2_g  = (const float*)d_in[9];
    const float* ln2_b  = (const float*)d_in[10];
    const float* fc_w   = (const float*)d_in[11];
    const float* fc_b   = (const float*)d_in[12];
    const float* out_w  = (const float*)d_in[13];
    const float* out_b  = (const float*)d_in[14];
    const float* lnf_g  = (const float*)d_in[15];
    const float* lnf_b  = (const float*)d_in[16];
    float* logits = (float*)d_out;

    cudaFuncSetAttribute(gemm_mma, cudaFuncAttributeMaxDynamicSharedMemorySize, SMEM_TOTAL);

    float *x, *ln, *attn, *qkv, *big;
    __nv_bfloat16 *ahi, *alo, *whi, *wlo;
    cudaGetSymbolAddress((void**)&x,    g_x);
    cudaGetSymbolAddress((void**)&ln,   g_ln);
    cudaGetSymbolAddress((void**)&attn, g_attn);
    cudaGetSymbolAddress((void**)&qkv,  g_qkv);
    cudaGetSymbolAddress((void**)&big,  g_big);
    cudaGetSymbolAddress((void**)&ahi,  g_ahi);
    cudaGetSymbolAddress((void**)&alo,  g_alo);
    cudaGetSymbolAddress((void**)&whi,  g_whi);
    cudaGetSymbolAddress((void**)&wlo,  g_wlo);

    embed_kernel<<<M, 256>>>(ids, wte, wpe);

    for (int l = 0; l < LAYERS; l++) {
        const float* aw = attn_w + (size_t)l * D * D3;
        const float* ab = attn_b + (size_t)l * D3;
        const float* pw = proj_w + (size_t)l * D * D;
        const float* pb = proj_b + (size_t)l * D;
        const float* fw = fc_w   + (size_t)l * D * D4;
        const float* fb = fc_b   + (size_t)l * D4;
        const float* ow = out_w  + (size_t)l * D4 * D;
        const float* ob = out_b  + (size_t)l * D;

        // attention block
        layernorm_kernel<<<M, 256>>>(x, ln1_g + (size_t)l * D, ln1_b + (size_t)l * D, ln);
        run_split(ln, ahi, alo, (size_t)M * D);
        run_wsplit(aw, whi, wlo, D, D3);
        run_gemm(ahi, alo, whi, wlo, ab, qkv, D3, D, 0);
        {
            dim3 grid(T, B * H);
            attention_kernel<<<grid, 128>>>(qkv, attn);
        }
        run_split(attn, ahi, alo, (size_t)M * D);
        run_wsplit(pw, whi, wlo, D, D);
        run_gemm(ahi, alo, whi, wlo, pb, x, D, D, FLAG_ACCUM);

        // mlp block
        layernorm_kernel<<<M, 256>>>(x, ln2_g + (size_t)l * D, ln2_b + (size_t)l * D, ln);
        run_split(ln, ahi, alo, (size_t)M * D);
        run_wsplit(fw, whi, wlo, D, D4);
        run_gemm(ahi, alo, whi, wlo, fb, big, D4, D, FLAG_GELU);
        run_split(big, ahi, alo, (size_t)M * D4);
        run_wsplit(ow, whi, wlo, D4, D);
        run_gemm(ahi, alo, whi, wlo, ob, x, D, D4, FLAG_ACCUM);
    }

    // final LN + tied lm_head: wte [V, D] is already [N, K] K-major — no transpose
    layernorm_kernel<<<M, 256>>>(x, lnf_g, lnf_b, ln);
    run_split(ln, ahi, alo, (size_t)M * D);
    run_split(wte, whi, wlo, (size_t)V * D);
    run_gemm(ahi, alo, whi, wlo, nullptr, logits, V, D, 0);
}